// round 10
// baseline (speedup 1.0000x reference)
#include <cuda_runtime.h>
#include <cstdint>

// PEPS 6x6, D=3, B=16 — quadrant decomposition, cluster of 2 CTAs per config,
// with row-pair step fusion. Left CTA (rank0): threads 0-255 = TL, 256-511 =
// BL. Right CTA: TR, BR (mirrored -> identical code). Per quadrant:
//   row 0 (sites 0-2): closed-form init (no steps)
//   rows 1-2: sites (3,4) and (6,7) fused via precomputed pair tensors
//     C[d0,d1,hp;u0,u1,h] = sum_m A3[d0,m,u0,h]*A4[d1,hp,u1,m]
//   -> only 4 barrier-separated contraction steps: apply34, site5, apply67, site8.
// C build shares the init step (both depend only on the gather).
// Merge P[j,k]=sum_v top[v,j]*bot[v,k] intra-CTA; one cross-CTA hop for Q.

#define NTH 512
#define ATF 108

__device__ __forceinline__ float dot3(float4 a, float4 b) {
    return a.x * b.x + a.y * b.y + a.z * b.z;
}

__device__ __forceinline__ uint32_t smem_u32(const void* p) {
    uint32_t a;
    asm("{ .reg .u64 t; cvta.to.shared.u64 t, %1; cvt.u32.u64 %0, t; }"
        : "=r"(a) : "l"(p));
    return a;
}

__device__ __forceinline__ void st_cluster_f32(uint32_t laddr, uint32_t rank, float v) {
    uint32_t r;
    asm volatile("mapa.shared::cluster.u32 %0, %1, %2;" : "=r"(r) : "r"(laddr), "r"(rank));
    asm volatile("st.shared::cluster.f32 [%0], %1;" :: "r"(r), "f"(v) : "memory");
}

__device__ __forceinline__ void mbar_init(uint32_t addr, uint32_t cnt) {
    asm volatile("mbarrier.init.shared.b64 [%0], %1;" :: "r"(addr), "r"(cnt) : "memory");
}

__device__ __forceinline__ void mbar_arrive_remote(uint32_t laddr, uint32_t rank) {
    asm volatile(
        "{ .reg .b32 ra;\n\t"
        "  mapa.shared::cluster.u32 ra, %0, %1;\n\t"
        "  mbarrier.arrive.shared::cluster.b64 _, [ra]; }"
        :: "r"(laddr), "r"(rank) : "memory");
}

__device__ __forceinline__ void mbar_wait0(uint32_t addr) {
    uint32_t done = 0;
    while (!done) {
        asm volatile(
            "{ .reg .pred p;\n\t"
            "  mbarrier.try_wait.parity.shared.b64 p, [%1], %2, 0x989680;\n\t"
            "  selp.b32 %0, 1, 0, p; }"
            : "=r"(done) : "r"(addr), "r"(0u) : "memory");
    }
}

#define FENCE_CLUSTER() asm volatile("fence.acq_rel.cluster;" ::: "memory")

__global__ __launch_bounds__(NTH, 1) __cluster_dims__(2, 1, 1)
void peps_quadf_kernel(const int* __restrict__ xcfg,
                       const float* __restrict__ T,
                       float* __restrict__ out) {
    __shared__ float4 S0[2][243];
    __shared__ float4 S1[2][243];
    __shared__ float4 Cb[2][2][243];    // [quadrant][pair][((d0*3+d1)*3+hp)*9+uu]
    __shared__ float  At[2][9 * ATF];
    __shared__ float  P[729];
    __shared__ float  QR[729];          // left CTA: remote writes only
    __shared__ int    spins[36];
    __shared__ int    sOff[36];
    __shared__ float  red[16];
    __shared__ uint64_t mb_q;

    const int t  = threadIdx.x;
    const int b  = blockIdx.x >> 1;
    const int qi = t >> 8;
    const int lt = t & 255;
    uint32_t rank;
    asm("mov.u32 %0, %%cluster_ctarank;" : "=r"(rank));
    const int right = (int)rank;

    const uint32_t a_mb = smem_u32(&mb_q);

    if (t < 36) spins[t] = xcfg[b * 36 + t];
    if (t == 0) mbar_init(a_mb, 1);
    __syncthreads();
    asm volatile("barrier.cluster.arrive.aligned;" ::: "memory");

    if (t < 36) {
        int xx = t / 6, yy = t % 6;
        int p  = spins[t];
        int pu = (xx > 0) ? spins[t - 6] : 0;
        int pd = (xx < 5) ? spins[t + 6] : 0;
        int pl = (yy > 0) ? spins[t - 1] : 0;
        int pr = (yy < 5) ? spins[t + 1] : 0;
        sOff[t] = (((p * 2 + pu) * 2 + pd) * 2 + pl) * 2 + pr;
    }
    __syncthreads();

    // Gather both quadrants' tensors: At[q][s][o][hp][a][ln].
    for (int i = t; i < 2 * 9 * ATF; i += NTH) {
        int q2 = i / 972, j = i - q2 * 972;
        int s = j / ATF, r = j - s * ATF;
        int o  = r / 36;  r -= o * 36;
        int hp = r / 12;  r -= hp * 12;
        int a  = r >> 2,  ln = r & 3;
        float v = 0.0f;
        if (ln < 3) {
            int x = q2    ? 5 - s / 3 : s / 3;
            int y = right ? 5 - s % 3 : s % 3;
            int u  = q2 ? o : a;
            int d  = q2 ? a : o;
            int l  = right ? hp : ln;
            int rr = right ? ln : hp;
            int site = x * 6 + y;
            v = T[site * 2592 + (((u * 3 + d) * 3 + l) * 3 + rr) * 32 + sOff[site]];
        }
        At[q2][j] = v;
    }
    __syncthreads();

    // Combined step: row-0 init (486 tasks) + pair-tensor builds (972 tasks).
    for (int i = t; i < 1458; i += NTH) {
        if (i < 486) {
            int q2 = i / 243, l2 = i - q2 * 243;
            float v = 0.0f;
            if (l2 % 3 == 0) {
                const float* Aq = At[q2];
                int d0 = l2 / 81, d1 = (l2 / 27) % 3, d2 = (l2 / 9) % 3, r2 = (l2 / 3) % 3;
                const float* A0 = Aq + d0 * 36;
                const float* A1 = Aq + ATF + d1 * 36;
                const float* A2 = Aq + 2 * ATF + d2 * 36 + r2 * 12;
                float w0 = A0[0] * A1[0]  + A0[12] * A1[1]  + A0[24] * A1[2];
                float w1 = A0[0] * A1[12] + A0[12] * A1[13] + A0[24] * A1[14];
                float w2 = A0[0] * A1[24] + A0[12] * A1[25] + A0[24] * A1[26];
                v = w0 * A2[0] + w1 * A2[1] + w2 * A2[2];
            }
            S0[q2][l2] = make_float4(v, 0.0f, 0.0f, 0.0f);
        } else {
            int j = i - 486;                 // 0..971
            int q2 = j / 486, k2 = j - q2 * 486;
            int pair = k2 / 243, k = k2 - pair * 243;
            int uu = k % 9, u0 = uu / 3, u1 = uu - 3 * u0;
            int dh = k / 9;                  // (d0*3+d1)*3 + hp
            int hp = dh % 3, dd = dh / 3, d0 = dd / 3, d1 = dd - 3 * d0;
            const float* Aq = At[q2];
            const float4* A3v = (const float4*)(Aq + (3 + pair * 3) * ATF) + d0 * 9 + u0;
            const float*  A4  = Aq + (4 + pair * 3) * ATF + d1 * 36 + hp * 12 + u1 * 4;
            float4 a0 = A3v[0], a1 = A3v[3], a2 = A3v[6];   // m = 0,1,2
            float  s0 = A4[0],  s1 = A4[1],  s2 = A4[2];
            Cb[q2][pair][k] = make_float4(
                a0.x * s0 + a1.x * s1 + a2.x * s2,
                a0.y * s0 + a1.y * s1 + a2.y * s2,
                a0.z * s0 + a1.z * s1 + a2.z * s2, 0.0f);
        }
    }
    asm volatile("barrier.cluster.wait.aligned;" ::: "memory");
    __syncthreads();

    // hoisted per-thread step indices (lt-based)
    const int d9  = (lt / 9) % 3,   b9  = lt - d9 * 9;
    const int r3  = lt % 3;
    const int bc4 = (lt / 27) * 27 + ((lt / 3) % 3) * 3;
    const int dd_ = lt / 27;        // d0*3 + d1
    const int ba  = lt % 27;        // digits below @27

    const float4* Atv = (const float4*)At[qi];
    float4* Sq0 = S0[qi];
    float4* Sq1 = S1[qi];

    // Fused pair step: contract digits @81 (u0) and @27 (u1) with C.
#define APPLY(PAIR, RD, WR) { \
    if (lt < 243) { \
        float4 c00 = (RD)[ba]; \
        float4 c01 = (RD)[ba + 27]; \
        float4 c02 = (RD)[ba + 54]; \
        float4 c10 = (RD)[ba + 81]; \
        float4 c11 = (RD)[ba + 108]; \
        float4 c12 = (RD)[ba + 135]; \
        float4 c20 = (RD)[ba + 162]; \
        float4 c21 = (RD)[ba + 189]; \
        float4 c22 = (RD)[ba + 216]; \
        const float4* Cq = Cb[qi][PAIR] + dd_ * 27; \
        float r0 = dot3(c00, Cq[0]) + dot3(c01, Cq[1]) + dot3(c02, Cq[2]) \
                 + dot3(c10, Cq[3]) + dot3(c11, Cq[4]) + dot3(c12, Cq[5]) \
                 + dot3(c20, Cq[6]) + dot3(c21, Cq[7]) + dot3(c22, Cq[8]); \
        float r1 = dot3(c00, Cq[9])  + dot3(c01, Cq[10]) + dot3(c02, Cq[11]) \
                 + dot3(c10, Cq[12]) + dot3(c11, Cq[13]) + dot3(c12, Cq[14]) \
                 + dot3(c20, Cq[15]) + dot3(c21, Cq[16]) + dot3(c22, Cq[17]); \
        float r2 = dot3(c00, Cq[18]) + dot3(c01, Cq[19]) + dot3(c02, Cq[20]) \
                 + dot3(c10, Cq[21]) + dot3(c11, Cq[22]) + dot3(c12, Cq[23]) \
                 + dot3(c20, Cq[24]) + dot3(c21, Cq[25]) + dot3(c22, Cq[26]); \
        (WR)[lt] = make_float4(r0, r1, r2, 0.0f); \
    } \
    __syncthreads(); \
}

#define STEPL(SITE, D_, BASE, S3, RD, WR) { \
    if (lt < 243) { \
        float4 c0 = (RD)[BASE]; \
        float4 c1 = (RD)[BASE + (S3)]; \
        float4 c2 = (RD)[BASE + 2 * (S3)]; \
        const float4* Av = Atv + (SITE) * 27 + (D_) * 9; \
        float r0 = dot3(c0, Av[0]) + dot3(c1, Av[1]) + dot3(c2, Av[2]); \
        float r1 = dot3(c0, Av[3]) + dot3(c1, Av[4]) + dot3(c2, Av[5]); \
        float r2 = dot3(c0, Av[6]) + dot3(c1, Av[7]) + dot3(c2, Av[8]); \
        (WR)[lt] = make_float4(r0, r1, r2, 0.0f); \
    } \
    __syncthreads(); \
}

#define STEPC4(SITE, RD, WR) { \
    if (lt < 243) { \
        const float4* Av = Atv + (SITE) * 27 + d9 * 9 + r3 * 3; \
        float s_ = dot3((RD)[bc4], Av[0]) + dot3((RD)[bc4 + 9], Av[1]) \
                 + dot3((RD)[bc4 + 18], Av[2]); \
        (WR)[lt] = make_float4(s_, 0.0f, 0.0f, 0.0f); \
    } \
    __syncthreads(); \
}

    APPLY (0,              Sq0, Sq1)    // sites 3+4
    STEPC4(5,              Sq1, Sq0)    // site 5
    APPLY (1,              Sq0, Sq1)    // sites 6+7
    STEPL (8, d9, b9, 9,   Sq1, Sq0)    // site 8; final state in S0[qi]
#undef APPLY
#undef STEPL
#undef STEPC4

    // Intra-CTA merge: P[j,k] = sum_{v<27} top[v*9+j/3].(j%3) * bot[v*9+k/3].(k%3)
    if (t < 243) {
        int j  = t / 9;
        int kg = t - 9 * j;
        int jg = j / 3, jl = j - 3 * jg;
        const float*  Stop = (const float*)S0[0];
        const float4* Sbot = S0[1];
        float a0 = 0.0f, a1 = 0.0f, a2 = 0.0f;
        #pragma unroll
        for (int v1 = 0; v1 < 27; ++v1) {
            float  l = Stop[(v1 * 9 + jg) * 4 + jl];
            float4 R = Sbot[v1 * 9 + kg];
            a0 += l * R.x; a1 += l * R.y; a2 += l * R.z;
        }
        int o = j * 27 + kg * 3;
        if (right) {
            uint32_t qa = smem_u32(QR) + (uint32_t)o * 4u;
            st_cluster_f32(qa,     0, a0);
            st_cluster_f32(qa + 4, 0, a1);
            st_cluster_f32(qa + 8, 0, a2);
        } else {
            P[o] = a0; P[o + 1] = a1; P[o + 2] = a2;
        }
    }
    __syncthreads();

    if (right) {
        if (t == 0) { FENCE_CLUSTER(); mbar_arrive_remote(a_mb, 0); }
        return;
    }

    // Left CTA: wait for Q, dot, write.
    mbar_wait0(a_mb);
    FENCE_CLUSTER();
    {
        float s = 0.0f;
        for (int v = t; v < 729; v += NTH) s += P[v] * QR[v];
        #pragma unroll
        for (int o = 16; o; o >>= 1) s += __shfl_xor_sync(0xFFFFFFFFu, s, o);
        if ((t & 31) == 0) red[t >> 5] = s;
        __syncthreads();
        if (t == 0) {
            float tt = 0.0f;
            #pragma unroll
            for (int w = 0; w < 16; ++w) tt += red[w];
            out[b] = tt;
        }
    }
}

extern "C" void kernel_launch(void* const* d_in, const int* in_sizes, int n_in,
                              void* d_out, int out_size) {
    const int*   xcfg = nullptr;
    const float* T    = nullptr;
    for (int i = 0; i < n_in; ++i) {
        if (in_sizes[i] == 576) xcfg = (const int*)d_in[i];
        else                    T    = (const float*)d_in[i];
    }
    float* out = (float*)d_out;
    peps_quadf_kernel<<<32, NTH>>>(xcfg, T, out);
}